// round 7
// baseline (speedup 1.0000x reference)
#include <cuda_runtime.h>
#include <cuda_bf16.h>

// AdderVDSR collapses analytically (established R0-R2, rel_err 1.2e-7):
//   relu(adder_conv) == 0 exactly after block 1 (sum of 576 |.| strictly
//   positive), so all 16 adder blocks emit zeros and
//   out[b,c] = out_b[c] + pixel_shuffle(conv3x3(x, up_w) + up_b, r=2).
//
// R6 = R4 layout (1 float4 out per thread, 98K threads, occ ~32%) +
//      R5's register-resident weights. R4's regs=32 build re-materialized
//      every weight LDG in-loop (90 LDG/thread, L1 20.5%); launch_bounds
//      minBlocks=1 releases the reg budget so the 54-float weight buffer
//      stays resident (one-shot 27x LDG.64).

__global__ __launch_bounds__(256, 1) void adder_vdsr_collapsed(
    const float* __restrict__ x,      // [2,3,128,128]
    const float* __restrict__ up_w,   // [12,3,3,3]
    const float* __restrict__ up_b,   // [12]
    const float* __restrict__ out_b,  // [3]
    float* __restrict__ out)          // [2,3,256,256]
{
    const int tx = threadIdx.x;                 // 0..63 -> conv col pair 2tx
    const int ty = threadIdx.y;                 // 0..3
    const int i  = blockIdx.y * 4 + ty;         // conv row 0..127
    const int z  = blockIdx.z;                  // 0..11
    const int b  = z / 6;
    const int cp = z - 6 * b;
    const int c  = cp >> 1;
    const int p  = cp & 1;
    const int o0 = 4 * c + 2 * p;
    const int j0 = 2 * tx;

    // 54 CTA-uniform weights for channels {o0, o0+1}: one-shot into registers.
    float wbuf[54];
    {
        const float2* Wv = reinterpret_cast<const float2*>(up_w + o0 * 27);
        #pragma unroll
        for (int k = 0; k < 27; k++) {
            float2 t = __ldg(Wv + k);
            wbuf[2 * k]     = t.x;
            wbuf[2 * k + 1] = t.y;
        }
    }
    const float bias0 = __ldg(up_b + o0);
    const float bias1 = __ldg(up_b + o0 + 1);
    const float ob    = __ldg(out_b + c);

    float a00 = bias0, a01 = bias0;   // channel o0, conv cols {j0, j0+1}
    float a10 = bias1, a11 = bias1;   // channel o0+1

    #pragma unroll
    for (int cin = 0; cin < 3; cin++) {
        const float* xp = x + (size_t)(b * 3 + cin) * 128 * 128;
        float v[3][4];                // rows ki, cols j0-1 .. j0+2
        #pragma unroll
        for (int ki = 0; ki < 3; ki++) {
            const int gi = i - 1 + ki;
            const bool rok = (gi >= 0) & (gi < 128);
            const float* rowp = xp + gi * 128;
            if (rok) {
                v[ki][0] = (tx > 0) ? __ldg(rowp + j0 - 1) : 0.0f;
                float2 m = __ldg(reinterpret_cast<const float2*>(rowp + j0));
                v[ki][1] = m.x;
                v[ki][2] = m.y;
                v[ki][3] = (tx < 63) ? __ldg(rowp + j0 + 2) : 0.0f;
            } else {
                v[ki][0] = v[ki][1] = v[ki][2] = v[ki][3] = 0.0f;
            }
        }
        #pragma unroll
        for (int ki = 0; ki < 3; ki++) {
            #pragma unroll
            for (int kj = 0; kj < 3; kj++) {
                const float w0 = wbuf[cin * 9 + ki * 3 + kj];       // ch o0
                const float w1 = wbuf[27 + cin * 9 + ki * 3 + kj];  // ch o0+1
                a00 = fmaf(v[ki][kj],     w0, a00);
                a10 = fmaf(v[ki][kj],     w1, a10);
                a01 = fmaf(v[ki][kj + 1], w0, a01);
                a11 = fmaf(v[ki][kj + 1], w1, a11);
            }
        }
    }

    // Pixel shuffle: conv col j -> out cols {2j, 2j+1}, channels {o0, o0+1}.
    // Thread covers out cols 4tx..4tx+3 of out-row (2i+p): one STG.128.
    float4 r = make_float4(a00 + ob, a10 + ob, a01 + ob, a11 + ob);
    float* row = out + ((size_t)(b * 3 + c) * 256 + (2 * i + p)) * 256;
    reinterpret_cast<float4*>(row)[tx] = r;
}

extern "C" void kernel_launch(void* const* d_in, const int* in_sizes, int n_in,
                              void* d_out, int out_size) {
    (void)in_sizes; (void)n_in; (void)out_size;
    const float* x     = (const float*)d_in[0];
    const float* up_w  = (const float*)d_in[1];
    const float* up_b  = (const float*)d_in[2];
    const float* out_b = (const float*)d_in[7];
    float* out = (float*)d_out;

    dim3 grid(1, 32, 12);   // 384 CTAs: y = conv-row/4, z = b*6 + c*2 + p
    dim3 block(64, 4);      // 256 threads; 98K threads total
    adder_vdsr_collapsed<<<grid, block>>>(x, up_w, up_b, out_b, out);
}